// round 16
// baseline (speedup 1.0000x reference)
#include <cuda_runtime.h>
#include <cuda_fp16.h>
#include <mma.h>
using namespace nvcuda;

#define Bn 64
#define Sn 512
#define Hn 768
#define H4 192
#define HU4 96
#define Cn 50
#define Mn 2000
#define Tn 32768

#define MCAP 512
#define UCAP 1024
#define NCAP 128
#define LCAP 128
#define MWCAP 48
#define UWCAP 80
#define USPLIT 8
#define GT 96

// ---------------- scratch ----------------------------------------------------
__device__ __align__(16) float g_nts[Tn];
__device__ __align__(16) float g_mts[Tn];
__device__ __align__(16) float g_uts[Tn];
__device__ __align__(16) float g_pm[Tn];
__device__ __align__(16) __half g_se_h[(size_t)Tn * Hn];      // 50 MB fp16 story
__device__ __align__(16) float g_names_emb[Cn * Bn * Hn];     // 9.8 MB
__device__ float g_nscore[Cn * Bn];
__device__ int   g_n_idx[Cn * NCAP];
__device__ int   g_n_cnt[Cn];
__device__ int   g_m_idx[Mn * MCAP];
__device__ float g_m_w[Mn * MCAP];
__device__ int   g_m_cnt[Mn];
__device__ float g_m_score[Mn];
__device__ __align__(16) float g_m_emb[(size_t)Mn * Hn];      // 6.1 MB
__device__ int   g_u_idx[Cn * UCAP];
__device__ float g_u_w[Cn * UCAP];
__device__ int   g_u_cnt[Cn];
__device__ __align__(16) float g_u_part[Cn * USPLIT * Hn];

__device__ __forceinline__ float wsum(float v) {
    for (int o = 16; o; o >>= 1) v += __shfl_xor_sync(0xffffffffu, v, o);
    return v;
}
__device__ __forceinline__ float wmaxr(float v) {
    for (int o = 16; o; o >>= 1) v = fmaxf(v, __shfl_xor_sync(0xffffffffu, v, o));
    return v;
}

__device__ __forceinline__ void h8fma(float* acc, float w, uint4 r) {
    __half2 h0 = *(__half2*)&r.x;
    __half2 h1 = *(__half2*)&r.y;
    __half2 h2 = *(__half2*)&r.z;
    __half2 h3 = *(__half2*)&r.w;
    float2 f0 = __half22float2(h0), f1 = __half22float2(h1);
    float2 f2 = __half22float2(h2), f3 = __half22float2(h3);
    acc[0] = fmaf(w, f0.x, acc[0]); acc[1] = fmaf(w, f0.y, acc[1]);
    acc[2] = fmaf(w, f1.x, acc[2]); acc[3] = fmaf(w, f1.y, acc[3]);
    acc[4] = fmaf(w, f2.x, acc[4]); acc[5] = fmaf(w, f2.y, acc[5]);
    acc[6] = fmaf(w, f3.x, acc[6]); acc[7] = fmaf(w, f3.y, acc[7]);
}

// ---------------- k_tok: 4 fused per-token dots + fp16 story copy -----------
__global__ void __launch_bounds__(256) k_tok(const float* __restrict__ se,
                      const float* __restrict__ wn,
                      const float* __restrict__ wm,
                      const float* __restrict__ wu,
                      const float* __restrict__ wpm) {
    __shared__ float s1[Hn], s2[Hn], s3[Hn], s4[Hn];
    for (int i = threadIdx.x; i < Hn; i += blockDim.x) {
        s1[i] = wn[i]; s2[i] = wm[i]; s3[i] = wu[i]; s4[i] = wpm[i];
    }
    __syncthreads();
    int warp = threadIdx.x >> 5, lane = threadIdx.x & 31;
    int t = blockIdx.x * 8 + warp;
    const float4* row = (const float4*)(se + (size_t)t * Hn);
    uint2* out_h = ((uint2*)g_se_h) + (size_t)t * H4;
    const float4* w1 = (const float4*)s1; const float4* w2 = (const float4*)s2;
    const float4* w3 = (const float4*)s3; const float4* w4 = (const float4*)s4;
    float a = 0.f, b = 0.f, c = 0.f, d = 0.f;
#pragma unroll
    for (int k = 0; k < 6; k++) {
        int i = lane + 32 * k;
        float4 x = row[i];
        float4 p = w1[i]; a += x.x * p.x + x.y * p.y + x.z * p.z + x.w * p.w;
        float4 q = w2[i]; b += x.x * q.x + x.y * q.y + x.z * q.z + x.w * q.w;
        float4 r = w3[i]; c += x.x * r.x + x.y * r.y + x.z * r.z + x.w * r.w;
        float4 u = w4[i]; d += x.x * u.x + x.y * u.y + x.z * u.z + x.w * u.w;
        __half2 h0 = __float22half2_rn(make_float2(x.x, x.y));
        __half2 h1 = __float22half2_rn(make_float2(x.z, x.w));
        uint2 packed; packed.x = *(unsigned*)&h0; packed.y = *(unsigned*)&h1;
        out_h[i] = packed;
    }
    a = wsum(a); b = wsum(b); c = wsum(c); d = wsum(d);
    if (lane == 0) { g_nts[t] = a; g_mts[t] = b; g_uts[t] = c; g_pm[t] = d; }
}

// ---------------- k_nscan ----------------------------------------------------
__global__ void __launch_bounds__(32) k_nscan(const float* __restrict__ nmask) {
    int c = blockIdx.x, lane = threadIdx.x;
    unsigned mlt = (1u << lane) - 1u;
    int cnt = 0;
    for (int base = 0; base < Sn; base += 32) {
        int s = base + lane;
        bool ok = (nmask[c * Sn + s] == 0.0f);
        unsigned bal = __ballot_sync(0xffffffffu, ok);
        if (ok) {
            int p = cnt + __popc(bal & mlt);
            if (p < NCAP) g_n_idx[c * NCAP + p] = s;
        }
        cnt += __popc(bal);
    }
    if (lane == 0) g_n_cnt[c] = min(cnt, NCAP);
}

// ---------------- k_scan: 1024 threads --------------------------------------
template <bool UTT>
__global__ void __launch_bounds__(1024) k_scan(const float* __restrict__ mask) {
    constexpr int CAP  = UTT ? UCAP : MCAP;
    constexpr int WCAP = UTT ? UWCAP : MWCAP;
    int r = blockIdx.x;
    __shared__ int   st_idx[32][WCAP];
    __shared__ float st_val[32][WCAP];
    __shared__ int wcnt[32];
    __shared__ int woff[32];
    __shared__ int s_n;
    __shared__ int   f_idx[CAP];
    __shared__ float f_val[CAP];
    __shared__ float s_red[32];
    int tid = threadIdx.x, warp = tid >> 5, lane = tid & 31;
    const float* tok = UTT ? g_uts : g_mts;
    const float4* m4 = (const float4*)(mask + (size_t)r * Tn);
    unsigned mlt = (1u << lane) - 1u;
    int cnt = 0;
    int base = warp * 256;
    for (int it = 0; it < 8; it++) {
        int i4 = base + it * 32 + lane;
        float4 v = m4[i4];
        bool o0 = (v.x == 0.f), o1 = (v.y == 0.f), o2 = (v.z == 0.f), o3 = (v.w == 0.f);
        unsigned b0 = __ballot_sync(0xffffffffu, o0);
        unsigned b1 = __ballot_sync(0xffffffffu, o1);
        unsigned b2 = __ballot_sync(0xffffffffu, o2);
        unsigned b3 = __ballot_sync(0xffffffffu, o3);
        int before = cnt + __popc(b0 & mlt) + __popc(b1 & mlt) + __popc(b2 & mlt) + __popc(b3 & mlt);
        int t0 = i4 * 4, k = 0;
        if (o0) { int p = before + k; if (p < WCAP) { st_idx[warp][p] = t0;     st_val[warp][p] = tok[t0];     } k++; }
        if (o1) { int p = before + k; if (p < WCAP) { st_idx[warp][p] = t0 + 1; st_val[warp][p] = tok[t0 + 1]; } k++; }
        if (o2) { int p = before + k; if (p < WCAP) { st_idx[warp][p] = t0 + 2; st_val[warp][p] = tok[t0 + 2]; } k++; }
        if (o3) { int p = before + k; if (p < WCAP) { st_idx[warp][p] = t0 + 3; st_val[warp][p] = tok[t0 + 3]; } k++; }
        cnt += __popc(b0) + __popc(b1) + __popc(b2) + __popc(b3);
    }
    if (lane == 0) wcnt[warp] = min(cnt, WCAP);
    __syncthreads();
    if (tid == 0) {
        int s = 0;
        for (int w = 0; w < 32; w++) { woff[w] = s; s += wcnt[w]; }
        s_n = min(s, CAP);
    }
    __syncthreads();
    {
        int off = woff[warp], wc = wcnt[warp];
        for (int j = lane; j < wc; j += 32) {
            int p = off + j;
            if (p < CAP) { f_idx[p] = st_idx[warp][j]; f_val[p] = st_val[warp][j]; }
        }
    }
    __syncthreads();
    int n = s_n;
    if (n > 0) {
        float mx = -3.4e38f;
        for (int j = tid; j < n; j += 1024) mx = fmaxf(mx, f_val[j]);
        mx = wmaxr(mx);
        if (lane == 0) s_red[warp] = mx;
        __syncthreads();
        if (warp == 0) { float v = s_red[lane]; v = wmaxr(v); if (lane == 0) s_red[0] = v; }
        __syncthreads();
        mx = s_red[0];
        __syncthreads();
        float sm = 0.f;
        for (int j = tid; j < n; j += 1024) sm += expf(f_val[j] - mx);
        sm = wsum(sm);
        if (lane == 0) s_red[warp] = sm;
        __syncthreads();
        if (warp == 0) { float v = s_red[lane]; v = wsum(v); if (lane == 0) s_red[0] = v; }
        __syncthreads();
        float inv = 1.0f / s_red[0];
        __syncthreads();
        if (UTT) {
            for (int j = tid; j < n; j += 1024) {
                g_u_idx[r * UCAP + j] = f_idx[j];
                g_u_w[r * UCAP + j] = expf(f_val[j] - mx) * inv;
            }
        } else {
            float psc = 0.f;
            for (int j = tid; j < n; j += 1024) {
                float w = expf(f_val[j] - mx) * inv;
                g_m_idx[r * MCAP + j] = f_idx[j];
                g_m_w[r * MCAP + j] = w;
                psc += w * g_pm[f_idx[j]];
            }
            psc = wsum(psc);
            if (lane == 0) s_red[warp] = psc;
            __syncthreads();
            if (warp == 0) { float v = s_red[lane]; v = wsum(v); if (lane == 0) g_m_score[r] = v; }
        }
    } else if (!UTT) {
        if (tid == 0) g_m_score[r] = 0.f;
    }
    if (tid == 0) { if (UTT) g_u_cnt[r] = n; else g_m_cnt[r] = n; }
}

// ---------------- k_names: per (c,b) pool, precompacted list ----------------
__global__ void __launch_bounds__(192) k_names(const float* __restrict__ w_name) {
    int c = blockIdx.x, b = blockIdx.y;
    int tid = threadIdx.x, warp = tid >> 5, lane = tid & 31;
    __shared__ int s_idx[NCAP];
    __shared__ float s_w[NCAP];
    __shared__ int s_cnt;
    __shared__ float sb[GT * 8];
    __shared__ float s_red[4];
    if (warp == 0) {
        int cnt = g_n_cnt[c];
        if (lane == 0) s_cnt = cnt;
        for (int j = lane; j < cnt; j += 32) {
            int s = g_n_idx[c * NCAP + j];
            s_idx[j] = s;
            s_w[j] = g_nts[b * Sn + s];
        }
        __syncwarp();
        float mx = -3.4e38f;
        for (int j = lane; j < cnt; j += 32) mx = fmaxf(mx, s_w[j]);
        mx = wmaxr(mx);
        float sm = 0.f;
        for (int j = lane; j < cnt; j += 32) sm += expf(s_w[j] - mx);
        sm = wsum(sm);
        float inv = 1.0f / sm;
        for (int j = lane; j < cnt; j += 32) s_w[j] = expf(s_w[j] - mx) * inv;
    }
    __syncthreads();
    int n = s_cnt;
    int g = tid / GT, gt = tid - g * GT;
    int j0 = g ? (n / 2) : 0;
    int j1 = g ? n : (n / 2);
    const uint4* se = (const uint4*)g_se_h;
    size_t rb = (size_t)b * Sn * HU4;
    float acc[8];
#pragma unroll
    for (int k = 0; k < 8; k++) acc[k] = 0.f;
    int j = j0;
    for (; j + 4 <= j1; j += 4) {
        uint4 r0 = se[rb + (size_t)s_idx[j]     * HU4 + gt];
        uint4 r1 = se[rb + (size_t)s_idx[j + 1] * HU4 + gt];
        uint4 r2 = se[rb + (size_t)s_idx[j + 2] * HU4 + gt];
        uint4 r3 = se[rb + (size_t)s_idx[j + 3] * HU4 + gt];
        h8fma(acc, s_w[j], r0); h8fma(acc, s_w[j + 1], r1);
        h8fma(acc, s_w[j + 2], r2); h8fma(acc, s_w[j + 3], r3);
    }
    for (; j < j1; j++) {
        uint4 r = se[rb + (size_t)s_idx[j] * HU4 + gt];
        h8fma(acc, s_w[j], r);
    }
    if (g == 1) {
#pragma unroll
        for (int k = 0; k < 8; k++) sb[gt * 8 + k] = acc[k];
    }
    __syncthreads();
    if (g == 0) {
#pragma unroll
        for (int k = 0; k < 8; k++) acc[k] += sb[gt * 8 + k];
        float4 lo = make_float4(acc[0], acc[1], acc[2], acc[3]);
        float4 hi = make_float4(acc[4], acc[5], acc[6], acc[7]);
        float4* dst = ((float4*)g_names_emb) + ((size_t)(c * Bn + b)) * H4 + gt * 2;
        dst[0] = lo; dst[1] = hi;
        const float4* wn4 = (const float4*)w_name;
        float4 wl = wn4[gt * 2], wh = wn4[gt * 2 + 1];
        float p = acc[0] * wl.x + acc[1] * wl.y + acc[2] * wl.z + acc[3] * wl.w
                + acc[4] * wh.x + acc[5] * wh.y + acc[6] * wh.z + acc[7] * wh.w;
        p = wsum(p);
        if (lane == 0) s_red[warp] = p;
    }
    __syncthreads();
    if (tid == 0) g_nscore[c * Bn + b] = s_red[0] + s_red[1] + s_red[2];
}

// ---------------- k_memb: per-mention weighted sum via HMMA -----------------
// Stage 16 gathered rows into smem per K-chunk; A row0 = weights; fp32 accum.
__global__ void __launch_bounds__(256) k_memb() {
    int m = blockIdx.x, tid = threadIdx.x, warp = tid >> 5, lane = tid & 31;
    __shared__ __half Xs[16 * Hn];    // 24 KB
    __shared__ __half As[16 * 16];    // 512 B
    __shared__ int   s_idx[MCAP];
    __shared__ float s_w[MCAP];
    __shared__ float slab[8][256];    // per-warp 16x16 f32 staging
    int n = g_m_cnt[m];
    int nch = (n + 15) >> 4;
    int npad = nch << 4;
    for (int j = tid; j < npad; j += 256) {
        if (j < n) { s_idx[j] = g_m_idx[m * MCAP + j]; s_w[j] = g_m_w[m * MCAP + j]; }
        else       { s_idx[j] = 0; s_w[j] = 0.f; }
    }
    if (tid < 64) ((uint2*)As)[tid] = make_uint2(0u, 0u);   // zero 16x16 halves
    __syncthreads();
    wmma::fragment<wmma::accumulator, 16, 16, 16, float> acc[6];
#pragma unroll
    for (int t = 0; t < 6; t++) wmma::fill_fragment(acc[t], 0.0f);

    for (int kc = 0; kc < nch; kc++) {
        // stage 16 story rows (16 x 96 uint4 = 1536 uint4, coalesced per row)
        for (int u = tid; u < 16 * HU4; u += 256) {
            int r = u / HU4, c = u - r * HU4;
            ((uint4*)Xs)[u] = ((const uint4*)g_se_h)[(size_t)s_idx[kc * 16 + r] * HU4 + c];
        }
        if (tid < 16) As[tid] = __float2half(s_w[kc * 16 + tid]);  // row 0 = weights
        __syncthreads();
        wmma::fragment<wmma::matrix_a, 16, 16, 16, __half, wmma::row_major> fa;
        wmma::load_matrix_sync(fa, As, 16);
#pragma unroll
        for (int t = 0; t < 6; t++) {
            wmma::fragment<wmma::matrix_b, 16, 16, 16, __half, wmma::row_major> fb;
            wmma::load_matrix_sync(fb, Xs + (warp * 6 + t) * 16, Hn);
            wmma::mma_sync(acc[t], fa, fb, acc[t]);
        }
        __syncthreads();
    }
    // row 0 of each accumulator tile -> g_m_emb
#pragma unroll
    for (int t = 0; t < 6; t++) {
        wmma::store_matrix_sync(slab[warp], acc[t], 16, wmma::mem_row_major);
        __syncwarp();
        if (lane < 16)
            g_m_emb[(size_t)m * Hn + (warp * 6 + t) * 16 + lane] = slab[warp][lane];
        __syncwarp();
    }
}

// ---------------- k_upart: utterance gather ---------------------------------
__global__ void __launch_bounds__(192) k_upart() {
    int c = blockIdx.x, q = blockIdx.y, tid = threadIdx.x;
    int n = g_u_cnt[c];
    int g = tid / GT, gt = tid - g * GT;
    int K = (n - q + USPLIT - 1) / USPLIT;
    if (K < 0) K = 0;
    int k0 = g ? (K / 2) : 0;
    int k1 = g ? K : (K / 2);
    const uint4* se = (const uint4*)g_se_h;
    float acc[8];
#pragma unroll
    for (int k = 0; k < 8; k++) acc[k] = 0.f;
    int k = k0;
    for (; k + 2 <= k1; k += 2) {
        int ja = q + k * USPLIT, jb = q + (k + 1) * USPLIT;
        int ta = g_u_idx[c * UCAP + ja];
        int tb = g_u_idx[c * UCAP + jb];
        float wa = g_u_w[c * UCAP + ja];
        float wb = g_u_w[c * UCAP + jb];
        uint4 ra = se[(size_t)ta * HU4 + gt];
        uint4 rb = se[(size_t)tb * HU4 + gt];
        h8fma(acc, wa, ra); h8fma(acc, wb, rb);
    }
    for (; k < k1; k++) {
        int j = q + k * USPLIT;
        int t = g_u_idx[c * UCAP + j];
        float w = g_u_w[c * UCAP + j];
        uint4 r = se[(size_t)t * HU4 + gt];
        h8fma(acc, w, r);
    }
    __shared__ float sb[GT * 8];
    if (g == 1) {
#pragma unroll
        for (int kk = 0; kk < 8; kk++) sb[gt * 8 + kk] = acc[kk];
    }
    __syncthreads();
    if (g == 0) {
#pragma unroll
        for (int kk = 0; kk < 8; kk++) acc[kk] += sb[gt * 8 + kk];
        float4 lo = make_float4(acc[0], acc[1], acc[2], acc[3]);
        float4 hi = make_float4(acc[4], acc[5], acc[6], acc[7]);
        float4* dst = ((float4*)g_u_part) + ((size_t)(c * USPLIT + q)) * H4 + gt * 2;
        dst[0] = lo; dst[1] = hi;
    }
}

// ---------------- k_final: per-char combine ---------------------------------
__global__ void __launch_bounds__(192) k_final(const int* __restrict__ seg,
                        const float* __restrict__ w_comb,
                        float* __restrict__ out) {
    int c = blockIdx.x, tid = threadIdx.x, warp = tid >> 5, lane = tid & 31;
    __shared__ float s_red[8];
    __shared__ float s_nw[Bn];
    __shared__ int s_list[LCAP];
    __shared__ float s_wgt[LCAP];
    __shared__ int s_n;
    __shared__ float s_a[3];
    __shared__ float s_parts[24];

    float mx = -3.4e38f;
    for (int b = tid; b < Bn; b += 192) mx = fmaxf(mx, g_nscore[c * Bn + b]);
    mx = wmaxr(mx);
    if (lane == 0) s_red[warp] = mx;
    __syncthreads();
    if (tid == 0) { float v = -3.4e38f; for (int w = 0; w < 6; w++) v = fmaxf(v, s_red[w]); s_red[0] = v; }
    __syncthreads();
    mx = s_red[0];
    __syncthreads();
    float sm = 0.f;
    for (int b = tid; b < Bn; b += 192) sm += expf(g_nscore[c * Bn + b] - mx);
    sm = wsum(sm);
    if (lane == 0) s_red[warp] = sm;
    __syncthreads();
    if (tid == 0) { float v = 0.f; for (int w = 0; w < 6; w++) v += s_red[w]; s_red[0] = v; }
    __syncthreads();
    float inv = 1.0f / s_red[0];
    for (int b = tid; b < Bn; b += 192) s_nw[b] = expf(g_nscore[c * Bn + b] - mx) * inv;
    __syncthreads();

    // mention segment softmax (warp0; Mn not 32-divisible -> guard tail)
    if (warp == 0) {
        unsigned mlt = (1u << lane) - 1u;
        int cnt = 0;
        for (int base = 0; base < Mn; base += 32) {
            int m = base + lane;
            bool ok = (m < Mn) && (seg[m] == c);
            unsigned bal = __ballot_sync(0xffffffffu, ok);
            if (ok) {
                int p = cnt + __popc(bal & mlt);
                if (p < LCAP) s_list[p] = m;
            }
            cnt += __popc(bal);
        }
        cnt = min(cnt, LCAP);
        if (lane == 0) s_n = cnt;
        __syncwarp();
        if (cnt > 0) {
            float m2 = -3.4e38f;
            for (int j = lane; j < cnt; j += 32) m2 = fmaxf(m2, g_m_score[s_list[j]]);
            m2 = wmaxr(m2);
            float sm2 = 0.f;
            for (int j = lane; j < cnt; j += 32) sm2 += expf(g_m_score[s_list[j]] - m2);
            sm2 = wsum(sm2);
            float inv2 = 1.0f / sm2;
            for (int j = lane; j < cnt; j += 32) s_wgt[j] = expf(g_m_score[s_list[j]] - m2) * inv2;
        }
    }
    __syncthreads();

    const float4* ne4 = (const float4*)g_names_emb;
    float4 aN = make_float4(0.f, 0.f, 0.f, 0.f);
    for (int b = 0; b < Bn; b++) {
        float w = s_nw[b];
        float4 x = ne4[((size_t)c * Bn + b) * H4 + tid];
        aN.x = fmaf(w, x.x, aN.x); aN.y = fmaf(w, x.y, aN.y);
        aN.z = fmaf(w, x.z, aN.z); aN.w = fmaf(w, x.w, aN.w);
    }
    int nm = s_n;
    const float4* me4 = (const float4*)g_m_emb;
    float4 aM = make_float4(0.f, 0.f, 0.f, 0.f);
    for (int j = 0; j < nm; j++) {
        float w = s_wgt[j];
        float4 x = me4[(size_t)s_list[j] * H4 + tid];
        aM.x = fmaf(w, x.x, aM.x); aM.y = fmaf(w, x.y, aM.y);
        aM.z = fmaf(w, x.z, aM.z); aM.w = fmaf(w, x.w, aM.w);
    }
    const float4* up4 = (const float4*)g_u_part;
    float4 aU = make_float4(0.f, 0.f, 0.f, 0.f);
    for (int q = 0; q < USPLIT; q++) {
        float4 x = up4[((size_t)(c * USPLIT + q)) * H4 + tid];
        aU.x += x.x; aU.y += x.y; aU.z += x.z; aU.w += x.w;
    }
    bool hasM = nm > 0;
    bool hasU = g_u_cnt[c] > 0;

    float4 wc4 = ((const float4*)w_comb)[tid];
    float p0 = aN.x * wc4.x + aN.y * wc4.y + aN.z * wc4.z + aN.w * wc4.w;
    float p1 = aM.x * wc4.x + aM.y * wc4.y + aM.z * wc4.z + aM.w * wc4.w;
    float p2 = aU.x * wc4.x + aU.y * wc4.y + aU.z * wc4.z + aU.w * wc4.w;
    p0 = wsum(p0); p1 = wsum(p1); p2 = wsum(p2);
    if (lane == 0) { s_parts[warp] = p0; s_parts[8 + warp] = p1; s_parts[16 + warp] = p2; }
    __syncthreads();
    if (tid == 0) {
        float s0 = 0.f, s1 = 0.f, s2 = 0.f;
        for (int w = 0; w < 6; w++) { s0 += s_parts[w]; s1 += s_parts[8 + w]; s2 += s_parts[16 + w]; }
        float m3 = s0;
        if (hasM) m3 = fmaxf(m3, s1);
        if (hasU) m3 = fmaxf(m3, s2);
        float e0 = expf(s0 - m3);
        float e1 = hasM ? expf(s1 - m3) : 0.0f;
        float e2 = hasU ? expf(s2 - m3) : 0.0f;
        float d = e0 + e1 + e2;
        s_a[0] = e0 / d; s_a[1] = e1 / d; s_a[2] = e2 / d;
    }
    __syncthreads();
    float a0 = s_a[0], a1 = s_a[1], a2 = s_a[2];
    float4 o;
    o.x = a0 * aN.x + a1 * aM.x + a2 * aU.x;
    o.y = a0 * aN.y + a1 * aM.y + a2 * aU.y;
    o.z = a0 * aN.z + a1 * aM.z + a2 * aU.z;
    o.w = a0 * aN.w + a1 * aM.w + a2 * aU.w;
    ((float4*)out)[(size_t)c * H4 + tid] = o;
}

// ---------------- launch -----------------------------------------------------
extern "C" void kernel_launch(void* const* d_in, const int* in_sizes, int n_in,
                              void* d_out, int out_size) {
    const float* se         = (const float*)d_in[0];
    const float* names_mask = (const float*)d_in[1];
    const float* utt_mask   = (const float*)d_in[2];
    const float* men_mask   = (const float*)d_in[3];
    const int*   seg        = (const int*)d_in[4];
    const float* w_name_tok = (const float*)d_in[5];
    const float* w_name     = (const float*)d_in[7];
    const float* w_men_tok  = (const float*)d_in[9];
    const float* w_men      = (const float*)d_in[11];
    const float* w_utt      = (const float*)d_in[13];
    const float* w_comb     = (const float*)d_in[15];
    float* out = (float*)d_out;

    k_tok<<<Tn / 8, 256>>>(se, w_name_tok, w_men_tok, w_utt, w_men);
    k_nscan<<<Cn, 32>>>(names_mask);
    k_names<<<dim3(Cn, Bn), 192>>>(w_name);
    k_scan<true><<<Cn, 1024>>>(utt_mask);
    k_upart<<<dim3(Cn, USPLIT), 192>>>();
    k_scan<false><<<Mn, 1024>>>(men_mask);
    k_memb<<<Mn, 256>>>();
    k_final<<<Cn, 192>>>(seg, w_comb, out);
}

// round 17
// speedup vs baseline: 2.1447x; 2.1447x over previous
#include <cuda_runtime.h>
#include <cuda_fp16.h>

#define Bn 64
#define Sn 512
#define Hn 768
#define H4 192
#define HU4 96
#define Cn 50
#define Mn 2000
#define Tn 32768

#define MCAP 512
#define UCAP 1024
#define NCAP 128
#define LCAP 128
#define MWCAP 48
#define UWCAP 80
#define USPLIT 8
#define GT 96

// ---------------- scratch ----------------------------------------------------
__device__ __align__(16) float g_nts[Tn];
__device__ __align__(16) float g_mts[Tn];
__device__ __align__(16) float g_uts[Tn];
__device__ __align__(16) float g_pm[Tn];
__device__ __align__(16) __half g_se_h[(size_t)Tn * Hn];      // 50 MB fp16 story
__device__ __align__(16) float g_names_emb[Cn * Bn * Hn];     // 9.8 MB
__device__ float g_nscore[Cn * Bn];
__device__ int   g_n_idx[Cn * NCAP];
__device__ int   g_n_cnt[Cn];
__device__ int   g_m_idx[Mn * MCAP];
__device__ float g_m_w[Mn * MCAP];
__device__ int   g_m_cnt[Mn];
__device__ float g_m_score[Mn];
__device__ __align__(16) float g_m_emb[(size_t)Mn * Hn];      // 6.1 MB
__device__ int   g_u_idx[Cn * UCAP];
__device__ float g_u_w[Cn * UCAP];
__device__ int   g_u_cnt[Cn];
__device__ __align__(16) float g_u_part[Cn * USPLIT * Hn];

__device__ __forceinline__ float wsum(float v) {
    for (int o = 16; o; o >>= 1) v += __shfl_xor_sync(0xffffffffu, v, o);
    return v;
}
__device__ __forceinline__ float wmaxr(float v) {
    for (int o = 16; o; o >>= 1) v = fmaxf(v, __shfl_xor_sync(0xffffffffu, v, o));
    return v;
}

__device__ __forceinline__ void h8fma(float* acc, float w, uint4 r) {
    __half2 h0 = *(__half2*)&r.x;
    __half2 h1 = *(__half2*)&r.y;
    __half2 h2 = *(__half2*)&r.z;
    __half2 h3 = *(__half2*)&r.w;
    float2 f0 = __half22float2(h0), f1 = __half22float2(h1);
    float2 f2 = __half22float2(h2), f3 = __half22float2(h3);
    acc[0] = fmaf(w, f0.x, acc[0]); acc[1] = fmaf(w, f0.y, acc[1]);
    acc[2] = fmaf(w, f1.x, acc[2]); acc[3] = fmaf(w, f1.y, acc[3]);
    acc[4] = fmaf(w, f2.x, acc[4]); acc[5] = fmaf(w, f2.y, acc[5]);
    acc[6] = fmaf(w, f3.x, acc[6]); acc[7] = fmaf(w, f3.y, acc[7]);
}

// ---------------- k_tok: 4 fused per-token dots + fp16 story copy -----------
__global__ void __launch_bounds__(256) k_tok(const float* __restrict__ se,
                      const float* __restrict__ wn,
                      const float* __restrict__ wm,
                      const float* __restrict__ wu,
                      const float* __restrict__ wpm) {
    __shared__ float s1[Hn], s2[Hn], s3[Hn], s4[Hn];
    for (int i = threadIdx.x; i < Hn; i += blockDim.x) {
        s1[i] = wn[i]; s2[i] = wm[i]; s3[i] = wu[i]; s4[i] = wpm[i];
    }
    __syncthreads();
    int warp = threadIdx.x >> 5, lane = threadIdx.x & 31;
    int t = blockIdx.x * 8 + warp;
    const float4* row = (const float4*)(se + (size_t)t * Hn);
    uint2* out_h = ((uint2*)g_se_h) + (size_t)t * H4;
    const float4* w1 = (const float4*)s1; const float4* w2 = (const float4*)s2;
    const float4* w3 = (const float4*)s3; const float4* w4 = (const float4*)s4;
    float a = 0.f, b = 0.f, c = 0.f, d = 0.f;
#pragma unroll
    for (int k = 0; k < 6; k++) {
        int i = lane + 32 * k;
        float4 x = row[i];
        float4 p = w1[i]; a += x.x * p.x + x.y * p.y + x.z * p.z + x.w * p.w;
        float4 q = w2[i]; b += x.x * q.x + x.y * q.y + x.z * q.z + x.w * q.w;
        float4 r = w3[i]; c += x.x * r.x + x.y * r.y + x.z * r.z + x.w * r.w;
        float4 u = w4[i]; d += x.x * u.x + x.y * u.y + x.z * u.z + x.w * u.w;
        __half2 h0 = __float22half2_rn(make_float2(x.x, x.y));
        __half2 h1 = __float22half2_rn(make_float2(x.z, x.w));
        uint2 packed; packed.x = *(unsigned*)&h0; packed.y = *(unsigned*)&h1;
        out_h[i] = packed;
    }
    a = wsum(a); b = wsum(b); c = wsum(c); d = wsum(d);
    if (lane == 0) { g_nts[t] = a; g_mts[t] = b; g_uts[t] = c; g_pm[t] = d; }
}

// ---------------- k_nscan ----------------------------------------------------
__global__ void __launch_bounds__(32) k_nscan(const float* __restrict__ nmask) {
    int c = blockIdx.x, lane = threadIdx.x;
    unsigned mlt = (1u << lane) - 1u;
    int cnt = 0;
    for (int base = 0; base < Sn; base += 32) {
        int s = base + lane;
        bool ok = (nmask[c * Sn + s] == 0.0f);
        unsigned bal = __ballot_sync(0xffffffffu, ok);
        if (ok) {
            int p = cnt + __popc(bal & mlt);
            if (p < NCAP) g_n_idx[c * NCAP + p] = s;
        }
        cnt += __popc(bal);
    }
    if (lane == 0) g_n_cnt[c] = min(cnt, NCAP);
}

// ---------------- k_scan: 1024 threads --------------------------------------
template <bool UTT>
__global__ void __launch_bounds__(1024) k_scan(const float* __restrict__ mask) {
    constexpr int CAP  = UTT ? UCAP : MCAP;
    constexpr int WCAP = UTT ? UWCAP : MWCAP;
    int r = blockIdx.x;
    __shared__ int   st_idx[32][WCAP];
    __shared__ float st_val[32][WCAP];
    __shared__ int wcnt[32];
    __shared__ int woff[32];
    __shared__ int s_n;
    __shared__ int   f_idx[CAP];
    __shared__ float f_val[CAP];
    __shared__ float s_red[32];
    int tid = threadIdx.x, warp = tid >> 5, lane = tid & 31;
    const float* tok = UTT ? g_uts : g_mts;
    const float4* m4 = (const float4*)(mask + (size_t)r * Tn);
    unsigned mlt = (1u << lane) - 1u;
    int cnt = 0;
    int base = warp * 256;
    for (int it = 0; it < 8; it++) {
        int i4 = base + it * 32 + lane;
        float4 v = m4[i4];
        bool o0 = (v.x == 0.f), o1 = (v.y == 0.f), o2 = (v.z == 0.f), o3 = (v.w == 0.f);
        unsigned b0 = __ballot_sync(0xffffffffu, o0);
        unsigned b1 = __ballot_sync(0xffffffffu, o1);
        unsigned b2 = __ballot_sync(0xffffffffu, o2);
        unsigned b3 = __ballot_sync(0xffffffffu, o3);
        int before = cnt + __popc(b0 & mlt) + __popc(b1 & mlt) + __popc(b2 & mlt) + __popc(b3 & mlt);
        int t0 = i4 * 4, k = 0;
        if (o0) { int p = before + k; if (p < WCAP) { st_idx[warp][p] = t0;     st_val[warp][p] = tok[t0];     } k++; }
        if (o1) { int p = before + k; if (p < WCAP) { st_idx[warp][p] = t0 + 1; st_val[warp][p] = tok[t0 + 1]; } k++; }
        if (o2) { int p = before + k; if (p < WCAP) { st_idx[warp][p] = t0 + 2; st_val[warp][p] = tok[t0 + 2]; } k++; }
        if (o3) { int p = before + k; if (p < WCAP) { st_idx[warp][p] = t0 + 3; st_val[warp][p] = tok[t0 + 3]; } k++; }
        cnt += __popc(b0) + __popc(b1) + __popc(b2) + __popc(b3);
    }
    if (lane == 0) wcnt[warp] = min(cnt, WCAP);
    __syncthreads();
    if (tid == 0) {
        int s = 0;
        for (int w = 0; w < 32; w++) { woff[w] = s; s += wcnt[w]; }
        s_n = min(s, CAP);
    }
    __syncthreads();
    {
        int off = woff[warp], wc = wcnt[warp];
        for (int j = lane; j < wc; j += 32) {
            int p = off + j;
            if (p < CAP) { f_idx[p] = st_idx[warp][j]; f_val[p] = st_val[warp][j]; }
        }
    }
    __syncthreads();
    int n = s_n;
    if (n > 0) {
        float mx = -3.4e38f;
        for (int j = tid; j < n; j += 1024) mx = fmaxf(mx, f_val[j]);
        mx = wmaxr(mx);
        if (lane == 0) s_red[warp] = mx;
        __syncthreads();
        if (warp == 0) { float v = s_red[lane]; v = wmaxr(v); if (lane == 0) s_red[0] = v; }
        __syncthreads();
        mx = s_red[0];
        __syncthreads();
        float sm = 0.f;
        for (int j = tid; j < n; j += 1024) sm += expf(f_val[j] - mx);
        sm = wsum(sm);
        if (lane == 0) s_red[warp] = sm;
        __syncthreads();
        if (warp == 0) { float v = s_red[lane]; v = wsum(v); if (lane == 0) s_red[0] = v; }
        __syncthreads();
        float inv = 1.0f / s_red[0];
        __syncthreads();
        if (UTT) {
            for (int j = tid; j < n; j += 1024) {
                g_u_idx[r * UCAP + j] = f_idx[j];
                g_u_w[r * UCAP + j] = expf(f_val[j] - mx) * inv;
            }
        } else {
            float psc = 0.f;
            for (int j = tid; j < n; j += 1024) {
                float w = expf(f_val[j] - mx) * inv;
                g_m_idx[r * MCAP + j] = f_idx[j];
                g_m_w[r * MCAP + j] = w;
                psc += w * g_pm[f_idx[j]];
            }
            psc = wsum(psc);
            if (lane == 0) s_red[warp] = psc;
            __syncthreads();
            if (warp == 0) { float v = s_red[lane]; v = wsum(v); if (lane == 0) g_m_score[r] = v; }
        }
    } else if (!UTT) {
        if (tid == 0) g_m_score[r] = 0.f;
    }
    if (tid == 0) { if (UTT) g_u_cnt[r] = n; else g_m_cnt[r] = n; }
}

// ---------------- k_names: per (c,b) pool, precompacted list ----------------
__global__ void __launch_bounds__(192) k_names(const float* __restrict__ w_name) {
    int c = blockIdx.x, b = blockIdx.y;
    int tid = threadIdx.x, warp = tid >> 5, lane = tid & 31;
    __shared__ int s_idx[NCAP];
    __shared__ float s_w[NCAP];
    __shared__ int s_cnt;
    __shared__ float sb[GT * 8];
    __shared__ float s_red[4];
    if (warp == 0) {
        int cnt = g_n_cnt[c];
        if (lane == 0) s_cnt = cnt;
        for (int j = lane; j < cnt; j += 32) {
            int s = g_n_idx[c * NCAP + j];
            s_idx[j] = s;
            s_w[j] = g_nts[b * Sn + s];
        }
        __syncwarp();
        float mx = -3.4e38f;
        for (int j = lane; j < cnt; j += 32) mx = fmaxf(mx, s_w[j]);
        mx = wmaxr(mx);
        float sm = 0.f;
        for (int j = lane; j < cnt; j += 32) sm += expf(s_w[j] - mx);
        sm = wsum(sm);
        float inv = 1.0f / sm;
        for (int j = lane; j < cnt; j += 32) s_w[j] = expf(s_w[j] - mx) * inv;
    }
    __syncthreads();
    int n = s_cnt;
    int g = tid / GT, gt = tid - g * GT;
    int j0 = g ? (n / 2) : 0;
    int j1 = g ? n : (n / 2);
    const uint4* se = (const uint4*)g_se_h;
    size_t rb = (size_t)b * Sn * HU4;
    float acc[8];
#pragma unroll
    for (int k = 0; k < 8; k++) acc[k] = 0.f;
    int j = j0;
    for (; j + 4 <= j1; j += 4) {
        uint4 r0 = se[rb + (size_t)s_idx[j]     * HU4 + gt];
        uint4 r1 = se[rb + (size_t)s_idx[j + 1] * HU4 + gt];
        uint4 r2 = se[rb + (size_t)s_idx[j + 2] * HU4 + gt];
        uint4 r3 = se[rb + (size_t)s_idx[j + 3] * HU4 + gt];
        h8fma(acc, s_w[j], r0); h8fma(acc, s_w[j + 1], r1);
        h8fma(acc, s_w[j + 2], r2); h8fma(acc, s_w[j + 3], r3);
    }
    for (; j < j1; j++) {
        uint4 r = se[rb + (size_t)s_idx[j] * HU4 + gt];
        h8fma(acc, s_w[j], r);
    }
    if (g == 1) {
#pragma unroll
        for (int k = 0; k < 8; k++) sb[gt * 8 + k] = acc[k];
    }
    __syncthreads();
    if (g == 0) {
#pragma unroll
        for (int k = 0; k < 8; k++) acc[k] += sb[gt * 8 + k];
        float4 lo = make_float4(acc[0], acc[1], acc[2], acc[3]);
        float4 hi = make_float4(acc[4], acc[5], acc[6], acc[7]);
        float4* dst = ((float4*)g_names_emb) + ((size_t)(c * Bn + b)) * H4 + gt * 2;
        dst[0] = lo; dst[1] = hi;
        const float4* wn4 = (const float4*)w_name;
        float4 wl = wn4[gt * 2], wh = wn4[gt * 2 + 1];
        float p = acc[0] * wl.x + acc[1] * wl.y + acc[2] * wl.z + acc[3] * wl.w
                + acc[4] * wh.x + acc[5] * wh.y + acc[6] * wh.z + acc[7] * wh.w;
        p = wsum(p);
        if (lane == 0) s_red[warp] = p;
    }
    __syncthreads();
    if (tid == 0) g_nscore[c * Bn + b] = s_red[0] + s_red[1] + s_red[2];
}

// ---------------- k_memb: per-mention gather (R9-proven form, no score) -----
__global__ void __launch_bounds__(192) k_memb() {
    int m = blockIdx.x, tid = threadIdx.x;
    __shared__ int s_idx[MCAP];
    __shared__ float s_w[MCAP];
    __shared__ float sb[GT * 8];
    int n = g_m_cnt[m];
    for (int j = tid; j < n; j += 192) {
        s_idx[j] = g_m_idx[m * MCAP + j];
        s_w[j]   = g_m_w[m * MCAP + j];
    }
    __syncthreads();
    int g = tid / GT, gt = tid - g * GT;
    int j0 = g ? (n / 2) : 0;
    int j1 = g ? n : (n / 2);
    const uint4* se = (const uint4*)g_se_h;
    float acc[8];
#pragma unroll
    for (int k = 0; k < 8; k++) acc[k] = 0.f;
    int j = j0;
    for (; j + 4 <= j1; j += 4) {
        uint4 r0 = se[(size_t)s_idx[j]     * HU4 + gt];
        uint4 r1 = se[(size_t)s_idx[j + 1] * HU4 + gt];
        uint4 r2 = se[(size_t)s_idx[j + 2] * HU4 + gt];
        uint4 r3 = se[(size_t)s_idx[j + 3] * HU4 + gt];
        h8fma(acc, s_w[j], r0); h8fma(acc, s_w[j + 1], r1);
        h8fma(acc, s_w[j + 2], r2); h8fma(acc, s_w[j + 3], r3);
    }
    for (; j < j1; j++) {
        uint4 r = se[(size_t)s_idx[j] * HU4 + gt];
        h8fma(acc, s_w[j], r);
    }
    if (g == 1) {
#pragma unroll
        for (int k = 0; k < 8; k++) sb[gt * 8 + k] = acc[k];
    }
    __syncthreads();
    if (g == 0) {
#pragma unroll
        for (int k = 0; k < 8; k++) acc[k] += sb[gt * 8 + k];
        float4 lo = make_float4(acc[0], acc[1], acc[2], acc[3]);
        float4 hi = make_float4(acc[4], acc[5], acc[6], acc[7]);
        float4* dst = ((float4*)g_m_emb) + (size_t)m * H4 + gt * 2;
        dst[0] = lo; dst[1] = hi;
    }
}

// ---------------- k_upart: utterance gather ---------------------------------
__global__ void __launch_bounds__(192) k_upart() {
    int c = blockIdx.x, q = blockIdx.y, tid = threadIdx.x;
    int n = g_u_cnt[c];
    int g = tid / GT, gt = tid - g * GT;
    int K = (n - q + USPLIT - 1) / USPLIT;
    if (K < 0) K = 0;
    int k0 = g ? (K / 2) : 0;
    int k1 = g ? K : (K / 2);
    const uint4* se = (const uint4*)g_se_h;
    float acc[8];
#pragma unroll
    for (int k = 0; k < 8; k++) acc[k] = 0.f;
    int k = k0;
    for (; k + 2 <= k1; k += 2) {
        int ja = q + k * USPLIT, jb = q + (k + 1) * USPLIT;
        int ta = g_u_idx[c * UCAP + ja];
        int tb = g_u_idx[c * UCAP + jb];
        float wa = g_u_w[c * UCAP + ja];
        float wb = g_u_w[c * UCAP + jb];
        uint4 ra = se[(size_t)ta * HU4 + gt];
        uint4 rb = se[(size_t)tb * HU4 + gt];
        h8fma(acc, wa, ra); h8fma(acc, wb, rb);
    }
    for (; k < k1; k++) {
        int j = q + k * USPLIT;
        int t = g_u_idx[c * UCAP + j];
        float w = g_u_w[c * UCAP + j];
        uint4 r = se[(size_t)t * HU4 + gt];
        h8fma(acc, w, r);
    }
    __shared__ float sb[GT * 8];
    if (g == 1) {
#pragma unroll
        for (int kk = 0; kk < 8; kk++) sb[gt * 8 + kk] = acc[kk];
    }
    __syncthreads();
    if (g == 0) {
#pragma unroll
        for (int kk = 0; kk < 8; kk++) acc[kk] += sb[gt * 8 + kk];
        float4 lo = make_float4(acc[0], acc[1], acc[2], acc[3]);
        float4 hi = make_float4(acc[4], acc[5], acc[6], acc[7]);
        float4* dst = ((float4*)g_u_part) + ((size_t)(c * USPLIT + q)) * H4 + gt * 2;
        dst[0] = lo; dst[1] = hi;
    }
}

// ---------------- k_final: per-char combine ---------------------------------
__global__ void __launch_bounds__(192) k_final(const int* __restrict__ seg,
                        const float* __restrict__ w_comb,
                        float* __restrict__ out) {
    int c = blockIdx.x, tid = threadIdx.x, warp = tid >> 5, lane = tid & 31;
    __shared__ float s_red[8];
    __shared__ float s_nw[Bn];
    __shared__ int s_list[LCAP];
    __shared__ float s_wgt[LCAP];
    __shared__ int s_n;
    __shared__ float s_a[3];
    __shared__ float s_parts[24];

    float mx = -3.4e38f;
    for (int b = tid; b < Bn; b += 192) mx = fmaxf(mx, g_nscore[c * Bn + b]);
    mx = wmaxr(mx);
    if (lane == 0) s_red[warp] = mx;
    __syncthreads();
    if (tid == 0) { float v = -3.4e38f; for (int w = 0; w < 6; w++) v = fmaxf(v, s_red[w]); s_red[0] = v; }
    __syncthreads();
    mx = s_red[0];
    __syncthreads();
    float sm = 0.f;
    for (int b = tid; b < Bn; b += 192) sm += expf(g_nscore[c * Bn + b] - mx);
    sm = wsum(sm);
    if (lane == 0) s_red[warp] = sm;
    __syncthreads();
    if (tid == 0) { float v = 0.f; for (int w = 0; w < 6; w++) v += s_red[w]; s_red[0] = v; }
    __syncthreads();
    float inv = 1.0f / s_red[0];
    for (int b = tid; b < Bn; b += 192) s_nw[b] = expf(g_nscore[c * Bn + b] - mx) * inv;
    __syncthreads();

    // mention segment softmax (warp0; Mn not 32-divisible -> guard tail)
    if (warp == 0) {
        unsigned mlt = (1u << lane) - 1u;
        int cnt = 0;
        for (int base = 0; base < Mn; base += 32) {
            int m = base + lane;
            bool ok = (m < Mn) && (seg[m] == c);
            unsigned bal = __ballot_sync(0xffffffffu, ok);
            if (ok) {
                int p = cnt + __popc(bal & mlt);
                if (p < LCAP) s_list[p] = m;
            }
            cnt += __popc(bal);
        }
        cnt = min(cnt, LCAP);
        if (lane == 0) s_n = cnt;
        __syncwarp();
        if (cnt > 0) {
            float m2 = -3.4e38f;
            for (int j = lane; j < cnt; j += 32) m2 = fmaxf(m2, g_m_score[s_list[j]]);
            m2 = wmaxr(m2);
            float sm2 = 0.f;
            for (int j = lane; j < cnt; j += 32) sm2 += expf(g_m_score[s_list[j]] - m2);
            sm2 = wsum(sm2);
            float inv2 = 1.0f / sm2;
            for (int j = lane; j < cnt; j += 32) s_wgt[j] = expf(g_m_score[s_list[j]] - m2) * inv2;
        }
    }
    __syncthreads();

    const float4* ne4 = (const float4*)g_names_emb;
    float4 aN = make_float4(0.f, 0.f, 0.f, 0.f);
    for (int b = 0; b < Bn; b++) {
        float w = s_nw[b];
        float4 x = ne4[((size_t)c * Bn + b) * H4 + tid];
        aN.x = fmaf(w, x.x, aN.x); aN.y = fmaf(w, x.y, aN.y);
        aN.z = fmaf(w, x.z, aN.z); aN.w = fmaf(w, x.w, aN.w);
    }
    int nm = s_n;
    const float4* me4 = (const float4*)g_m_emb;
    float4 aM = make_float4(0.f, 0.f, 0.f, 0.f);
    for (int j = 0; j < nm; j++) {
        float w = s_wgt[j];
        float4 x = me4[(size_t)s_list[j] * H4 + tid];
        aM.x = fmaf(w, x.x, aM.x); aM.y = fmaf(w, x.y, aM.y);
        aM.z = fmaf(w, x.z, aM.z); aM.w = fmaf(w, x.w, aM.w);
    }
    const float4* up4 = (const float4*)g_u_part;
    float4 aU = make_float4(0.f, 0.f, 0.f, 0.f);
    for (int q = 0; q < USPLIT; q++) {
        float4 x = up4[((size_t)(c * USPLIT + q)) * H4 + tid];
        aU.x += x.x; aU.y += x.y; aU.z += x.z; aU.w += x.w;
    }
    bool hasM = nm > 0;
    bool hasU = g_u_cnt[c] > 0;

    float4 wc4 = ((const float4*)w_comb)[tid];
    float p0 = aN.x * wc4.x + aN.y * wc4.y + aN.z * wc4.z + aN.w * wc4.w;
    float p1 = aM.x * wc4.x + aM.y * wc4.y + aM.z * wc4.z + aM.w * wc4.w;
    float p2 = aU.x * wc4.x + aU.y * wc4.y + aU.z * wc4.z + aU.w * wc4.w;
    p0 = wsum(p0); p1 = wsum(p1); p2 = wsum(p2);
    if (lane == 0) { s_parts[warp] = p0; s_parts[8 + warp] = p1; s_parts[16 + warp] = p2; }
    __syncthreads();
    if (tid == 0) {
        float s0 = 0.f, s1 = 0.f, s2 = 0.f;
        for (int w = 0; w < 6; w++) { s0 += s_parts[w]; s1 += s_parts[8 + w]; s2 += s_parts[16 + w]; }
        float m3 = s0;
        if (hasM) m3 = fmaxf(m3, s1);
        if (hasU) m3 = fmaxf(m3, s2);
        float e0 = expf(s0 - m3);
        float e1 = hasM ? expf(s1 - m3) : 0.0f;
        float e2 = hasU ? expf(s2 - m3) : 0.0f;
        float d = e0 + e1 + e2;
        s_a[0] = e0 / d; s_a[1] = e1 / d; s_a[2] = e2 / d;
    }
    __syncthreads();
    float a0 = s_a[0], a1 = s_a[1], a2 = s_a[2];
    float4 o;
    o.x = a0 * aN.x + a1 * aM.x + a2 * aU.x;
    o.y = a0 * aN.y + a1 * aM.y + a2 * aU.y;
    o.z = a0 * aN.z + a1 * aM.z + a2 * aU.z;
    o.w = a0 * aN.w + a1 * aM.w + a2 * aU.w;
    ((float4*)out)[(size_t)c * H4 + tid] = o;
}

// ---------------- launch -----------------------------------------------------
extern "C" void kernel_launch(void* const* d_in, const int* in_sizes, int n_in,
                              void* d_out, int out_size) {
    const float* se         = (const float*)d_in[0];
    const float* names_mask = (const float*)d_in[1];
    const float* utt_mask   = (const float*)d_in[2];
    const float* men_mask   = (const float*)d_in[3];
    const int*   seg        = (const int*)d_in[4];
    const float* w_name_tok = (const float*)d_in[5];
    const float* w_name     = (const float*)d_in[7];
    const float* w_men_tok  = (const float*)d_in[9];
    const float* w_men      = (const float*)d_in[11];
    const float* w_utt      = (const float*)d_in[13];
    const float* w_comb     = (const float*)d_in[15];
    float* out = (float*)d_out;

    k_tok<<<Tn / 8, 256>>>(se, w_name_tok, w_men_tok, w_utt, w_men);
    k_nscan<<<Cn, 32>>>(names_mask);
    k_names<<<dim3(Cn, Bn), 192>>>(w_name);
    k_scan<true><<<Cn, 1024>>>(utt_mask);
    k_upart<<<dim3(Cn, USPLIT), 192>>>();
    k_scan<false><<<Mn, 1024>>>(men_mask);
    k_memb<<<Mn, 192>>>();
    k_final<<<Cn, 192>>>(seg, w_comb, out);
}